// round 10
// baseline (speedup 1.0000x reference)
#include <cuda_runtime.h>

// LatentODE2 R10: split-k two-warp CTAs. E=8 elems/CTA, 64 threads, 1024 CTAs
// -> 2048 warps (2x occupancy vs R8). Warp w owns k-half [16w, 16w+16) of the
// z1/g loops with WEIGHTS IN REGISTERS (no weight LDS at all). h rows read
// disjointly per warp. Partial accums exchanged via conflict-free SMEM once
// per Euler step. dh splits j (w0: 0-24, w1: 25-49). w0 = z-path combine/tanh/
// publish; w1 = g-combine + dy + dh-combine + h update + y output.

#define T_STEPS 100
#define D_IN    16
#define H_DIM   32
#define HD_DIM  50
#define EULER   10
#define STEP_F  0.1f
#define DTS_F   (1.0f / 24.0f)

#define E       8
#define KH      16          // k-half per warp
#define JH      25          // j-half per warp (dh loop)
#define GRID    1024        // 8192 / 8

typedef unsigned long long u64;

__device__ __forceinline__ u64 pk2(float lo, float hi) {
    u64 r; asm("mov.b64 %0, {%1, %2};" : "=l"(r) : "f"(lo), "f"(hi)); return r;
}
__device__ __forceinline__ void up2(u64 v, float& a, float& b) {
    asm("mov.b64 {%0, %1}, %2;" : "=f"(a), "=f"(b) : "l"(v));
}
__device__ __forceinline__ void fma2(u64& d, u64 a, u64 b) {
    asm("fma.rn.f32x2 %0, %1, %2, %0;" : "+l"(d) : "l"(a), "l"(b));
}
__device__ __forceinline__ u64 add2(u64 a, u64 b) {
    u64 r; asm("add.rn.f32x2 %0, %1, %2;" : "=l"(r) : "l"(a), "l"(b)); return r;
}
__device__ __forceinline__ float tanh_fast(float v) {
    float r; asm("tanh.approx.f32 %0, %1;" : "=f"(r) : "f"(v)); return r;
}
__device__ __forceinline__ u64 tanh2(u64 v) {
    float a, b; up2(v, a, b);
    return pk2(tanh_fast(a), tanh_fast(b));
}

__global__ void __launch_bounds__(64, 5)
latentode2_kernel(const float* __restrict__ dt,
                  const float* __restrict__ x,
                  const float* __restrict__ W1, const float* __restrict__ b1,
                  const float* __restrict__ W2, const float* __restrict__ b2,
                  const float* __restrict__ W3, const float* __restrict__ b3,
                  const float* __restrict__ W4, const float* __restrict__ b4,
                  float* __restrict__ out)
{
    // x-part weights (fp32, SMEM; amortized 1/10): sW1x[k*32+j] = (W1[j][k], W1[j+32][k])
    __shared__ float2 sW1x[16 * 32];
    // State rows: A = elems 0..3 (two f32x2), B = elems 4..7.
    __shared__ ulonglong2 sXA[D_IN],  sXB[D_IN];
    __shared__ ulonglong2 sHA[H_DIM], sHB[H_DIM];
    __shared__ ulonglong2 sZA[HD_DIM], sZB[HD_DIM];
    // Exchange buffers (component-major: conflict-free stride-8B across lanes).
    __shared__ u64 EXz[8][32];   // w1 -> w0: z partials
    __shared__ u64 EXg[8][32];   // w0 -> w1: g partials
    __shared__ u64 EXd[4][32];   // w0 -> w1: dh partials

    const int tid  = threadIdx.x;
    const int wid  = tid >> 5;
    const int lane = tid & 31;
    const int kb   = wid * KH;          // own k-half base (h row base too)
    const int jb   = wid * JH;          // own j-half base (dh loop)

    for (int idx = tid; idx < 16 * 32; idx += 64) {
        int k = idx >> 5, j = idx & 31;
        float hi = (j + 32 < HD_DIM) ? W1[(j + 32) * 48 + k] : 0.0f;
        sW1x[idx] = make_float2(W1[j * 48 + k], hi);
    }

    // Register weights for own k-half:
    //  wa/wb = W1[j][16+kb+i], W1[j+32][16+kb+i];  ua/ub = W3[j][kb+i], W3[j+32][kb+i]
    float wa[KH], wb[KH], ua[KH], ub[KH];
#pragma unroll
    for (int i = 0; i < KH; i++) {
        wa[i] = W1[lane * 48 + 16 + kb + i];
        wb[i] = (lane + 32 < HD_DIM) ? W1[(lane + 32) * 48 + 16 + kb + i] : 0.0f;
        ua[i] = W3[lane * 32 + kb + i];
        ub[i] = W3[(lane + 32) * 32 + kb + i];
    }
    // W2 half-row (dh output k = lane, own j-half).
    float w2r[JH];
#pragma unroll
    for (int j = 0; j < JH; j++) w2r[j] = W2[lane * HD_DIM + jb + j];

    const int e0 = blockIdx.x * E;

    const float b1lo = b1[lane];
    const float b1hi = (lane + 32 < HD_DIM) ? b1[lane + 32] : 0.0f;
    const u64 PB3lo = pk2(b3[lane], b3[lane]);
    const u64 PB3hi = pk2(b3[lane + 32], b3[lane + 32]);
    const float b2s = b2[lane];
    const u64 PB2 = pk2(b2s, b2s);
    const float b4v = b4[0];
    const float w4a = W4[lane];
    const float w4b = W4[lane + 32];

    // h master copy (w1 only uses it; harmless in w0).
    float h0 = 0, h1 = 0, h2 = 0, h3 = 0, h4 = 0, h5 = 0, h6 = 0, h7 = 0;
    if (wid == 1) {
        sHA[lane] = make_ulonglong2(0ull, 0ull);
        sHB[lane] = make_ulonglong2(0ull, 0ull);
    }
    __syncthreads();

    const float2* dt2 = (const float2*)dt;

    float cs[E];
    float p0 = 0, p1 = 0, p2 = 0, p3 = 0, p4 = 0, p5 = 0, p6 = 0, p7 = 0;
    float x0v[E];
    u64 zx[8];   // w0 only

#pragma unroll 1
    for (int t = 0; t < T_STEPS; t++) {
        // Stage x rows (w0 lanes 0..15).
        if (wid == 0 && lane < D_IN) {
            float xv[E];
#pragma unroll
            for (int e = 0; e < E; e++)
                xv[e] = x[((e0 + e) * T_STEPS + t) * D_IN + lane];
            sXA[lane] = make_ulonglong2(pk2(xv[0], xv[1]), pk2(xv[2], xv[3]));
            sXB[lane] = make_ulonglong2(pk2(xv[4], xv[5]), pk2(xv[6], xv[7]));
        }
        if (wid == 1) {
#pragma unroll
            for (int e = 0; e < E; e++) {
                float2 d = dt2[(e0 + e) * T_STEPS + t];
                cs[e] = STEP_F * ((d.y - d.x) * DTS_F);
            }
            p0 = p1 = p2 = p3 = p4 = p5 = p6 = p7 = 0.0f;
        }
        __syncthreads();   // x staged

        if (wid == 0) {
            // zx = b1 + x @ W1x^T (full x-part, w0 only; reused for 10 steps).
            zx[0] = pk2(b1lo, b1lo); zx[1] = zx[0]; zx[2] = zx[0]; zx[3] = zx[0];
            zx[4] = pk2(b1hi, b1hi); zx[5] = zx[4]; zx[6] = zx[4]; zx[7] = zx[4];
#pragma unroll
            for (int k = 0; k < D_IN; k++) {
                ulonglong2 vA = sXA[k], vB = sXB[k];
                float2 w = sW1x[k * 32 + lane];
                u64 wl = pk2(w.x, w.x), wh = pk2(w.y, w.y);
                fma2(zx[0], vA.x, wl); fma2(zx[1], vA.y, wl);
                fma2(zx[2], vB.x, wl); fma2(zx[3], vB.y, wl);
                fma2(zx[4], vA.x, wh); fma2(zx[5], vA.y, wh);
                fma2(zx[6], vB.x, wh); fma2(zx[7], vB.y, wh);
            }
        } else {
            // y init values.
            ulonglong2 vA = sXA[0], vB = sXB[0];
            up2(vA.x, x0v[0], x0v[1]); up2(vA.y, x0v[2], x0v[3]);
            up2(vB.x, x0v[4], x0v[5]); up2(vB.y, x0v[6], x0v[7]);
        }

#pragma unroll 1
        for (int s = 0; s < EULER; s++) {
            // Partial z1/g over own k-half; weights from registers.
            u64 zz[8], gg[8];
            if (wid == 0) {
#pragma unroll
                for (int c = 0; c < 8; c++) { zz[c] = zx[c]; gg[c] = 0ull; }
            } else {
#pragma unroll
                for (int c = 0; c < 8; c++) zz[c] = 0ull;
                gg[0] = PB3lo; gg[1] = PB3lo; gg[2] = PB3lo; gg[3] = PB3lo;
                gg[4] = PB3hi; gg[5] = PB3hi; gg[6] = PB3hi; gg[7] = PB3hi;
            }
#pragma unroll
            for (int i = 0; i < KH; i++) {
                ulonglong2 vA = sHA[kb + i], vB = sHB[kb + i];
                u64 wl = pk2(wa[i], wa[i]), wh = pk2(wb[i], wb[i]);
                u64 ul = pk2(ua[i], ua[i]), uh = pk2(ub[i], ub[i]);
                fma2(zz[0], vA.x, wl); fma2(zz[1], vA.y, wl);
                fma2(zz[2], vB.x, wl); fma2(zz[3], vB.y, wl);
                fma2(zz[4], vA.x, wh); fma2(zz[5], vA.y, wh);
                fma2(zz[6], vB.x, wh); fma2(zz[7], vB.y, wh);
                fma2(gg[0], vA.x, ul); fma2(gg[1], vA.y, ul);
                fma2(gg[2], vB.x, ul); fma2(gg[3], vB.y, ul);
                fma2(gg[4], vA.x, uh); fma2(gg[5], vA.y, uh);
                fma2(gg[6], vB.x, uh); fma2(gg[7], vB.y, uh);
            }

            // Exchange partials.
            if (wid == 0) {
#pragma unroll
                for (int c = 0; c < 8; c++) EXg[c][lane] = gg[c];
            } else {
#pragma unroll
                for (int c = 0; c < 8; c++) EXz[c][lane] = zz[c];
            }
            __syncthreads();   // (1) partials visible

            if (wid == 0) {
                // Combine z, tanh, publish.
#pragma unroll
                for (int c = 0; c < 8; c++) zz[c] = add2(zz[c], EXz[c][lane]);
                sZA[lane] = make_ulonglong2(tanh2(zz[0]), tanh2(zz[1]));
                sZB[lane] = make_ulonglong2(tanh2(zz[2]), tanh2(zz[3]));
                if (lane + 32 < HD_DIM) {
                    sZA[lane + 32] = make_ulonglong2(tanh2(zz[4]), tanh2(zz[5]));
                    sZB[lane + 32] = make_ulonglong2(tanh2(zz[6]), tanh2(zz[7]));
                }
            } else {
                // Combine g, accumulate dy partials.
#pragma unroll
                for (int c = 0; c < 8; c++) gg[c] = add2(gg[c], EXg[c][lane]);
                float a, b, c2, d2;
                up2(gg[0], a, b); up2(gg[4], c2, d2);
                p0 = fmaf(tanh_fast(a), w4a, fmaf(tanh_fast(c2), w4b, p0));
                p1 = fmaf(tanh_fast(b), w4a, fmaf(tanh_fast(d2), w4b, p1));
                up2(gg[1], a, b); up2(gg[5], c2, d2);
                p2 = fmaf(tanh_fast(a), w4a, fmaf(tanh_fast(c2), w4b, p2));
                p3 = fmaf(tanh_fast(b), w4a, fmaf(tanh_fast(d2), w4b, p3));
                up2(gg[2], a, b); up2(gg[6], c2, d2);
                p4 = fmaf(tanh_fast(a), w4a, fmaf(tanh_fast(c2), w4b, p4));
                p5 = fmaf(tanh_fast(b), w4a, fmaf(tanh_fast(d2), w4b, p5));
                up2(gg[3], a, b); up2(gg[7], c2, d2);
                p6 = fmaf(tanh_fast(a), w4a, fmaf(tanh_fast(c2), w4b, p6));
                p7 = fmaf(tanh_fast(b), w4a, fmaf(tanh_fast(d2), w4b, p7));
            }
            __syncthreads();   // (2) z published

            // dh partial over own j-half.
            u64 dd[4];
            if (wid == 1) { dd[0] = PB2; dd[1] = PB2; dd[2] = PB2; dd[3] = PB2; }
            else          { dd[0] = 0;   dd[1] = 0;   dd[2] = 0;   dd[3] = 0;  }
#pragma unroll
            for (int j = 0; j < JH; j++) {
                ulonglong2 zA = sZA[jb + j], zB = sZB[jb + j];
                u64 wd = pk2(w2r[j], w2r[j]);
                fma2(dd[0], zA.x, wd); fma2(dd[1], zA.y, wd);
                fma2(dd[2], zB.x, wd); fma2(dd[3], zB.y, wd);
            }
            if (wid == 0) {
#pragma unroll
                for (int c = 0; c < 4; c++) EXd[c][lane] = dd[c];
            }
            __syncthreads();   // (3) dh partials visible

            if (wid == 1) {
#pragma unroll
                for (int c = 0; c < 4; c++) dd[c] = add2(dd[c], EXd[c][lane]);
                float a, b;
                up2(dd[0], a, b); h0 = fmaf(cs[0], tanh_fast(a), h0);
                                  h1 = fmaf(cs[1], tanh_fast(b), h1);
                up2(dd[1], a, b); h2 = fmaf(cs[2], tanh_fast(a), h2);
                                  h3 = fmaf(cs[3], tanh_fast(b), h3);
                up2(dd[2], a, b); h4 = fmaf(cs[4], tanh_fast(a), h4);
                                  h5 = fmaf(cs[5], tanh_fast(b), h5);
                up2(dd[3], a, b); h6 = fmaf(cs[6], tanh_fast(a), h6);
                                  h7 = fmaf(cs[7], tanh_fast(b), h7);
                sHA[lane] = make_ulonglong2(pk2(h0, h1), pk2(h2, h3));
                sHB[lane] = make_ulonglong2(pk2(h4, h5), pk2(h6, h7));
            }
            __syncthreads();   // (4) h published
        }

        // y output (w1): reduce p once per t-step.
        if (wid == 1) {
#pragma unroll
            for (int off = 16; off > 0; off >>= 1) {
                p0 += __shfl_xor_sync(0xffffffffu, p0, off);
                p1 += __shfl_xor_sync(0xffffffffu, p1, off);
                p2 += __shfl_xor_sync(0xffffffffu, p2, off);
                p3 += __shfl_xor_sync(0xffffffffu, p3, off);
                p4 += __shfl_xor_sync(0xffffffffu, p4, off);
                p5 += __shfl_xor_sync(0xffffffffu, p5, off);
                p6 += __shfl_xor_sync(0xffffffffu, p6, off);
                p7 += __shfl_xor_sync(0xffffffffu, p7, off);
            }
            const float eb4 = (float)EULER * b4v;
            float yv = fmaf(cs[0], p0 + eb4, x0v[0]);
            if (lane == 1) yv = fmaf(cs[1], p1 + eb4, x0v[1]);
            if (lane == 2) yv = fmaf(cs[2], p2 + eb4, x0v[2]);
            if (lane == 3) yv = fmaf(cs[3], p3 + eb4, x0v[3]);
            if (lane == 4) yv = fmaf(cs[4], p4 + eb4, x0v[4]);
            if (lane == 5) yv = fmaf(cs[5], p5 + eb4, x0v[5]);
            if (lane == 6) yv = fmaf(cs[6], p6 + eb4, x0v[6]);
            if (lane == 7) yv = fmaf(cs[7], p7 + eb4, x0v[7]);
            if (lane < E) out[(e0 + lane) * T_STEPS + t] = yv;
        }
        // Next t's staging is ordered by the top-of-loop __syncthreads.
    }
}

extern "C" void kernel_launch(void* const* d_in, const int* in_sizes, int n_in,
                              void* d_out, int out_size) {
    (void)in_sizes; (void)n_in; (void)out_size;
    const float* dt = (const float*)d_in[0];
    const float* x  = (const float*)d_in[1];
    const float* W1 = (const float*)d_in[2];
    const float* b1 = (const float*)d_in[3];
    const float* W2 = (const float*)d_in[4];
    const float* b2 = (const float*)d_in[5];
    const float* W3 = (const float*)d_in[6];
    const float* b3 = (const float*)d_in[7];
    const float* W4 = (const float*)d_in[8];
    const float* b4 = (const float*)d_in[9];
    float* out = (float*)d_out;

    latentode2_kernel<<<GRID, 64>>>(
        dt, x, W1, b1, W2, b2, W3, b3, W4, b4, out);
}

// round 14
// speedup vs baseline: 1.7062x; 1.7062x over previous
#include <cuda_runtime.h>

// LatentODE2 R11: exactly R8 (best: 2049us; E=8/warp, 1-warp CTAs, f32x2
// output-lane pairs, approx-tanh, zx/p hoists, W2-in-regs, fp32 h/z state)
// with ONE change: sW13 h-loop weights stored bf16-packed (u64 = 4 weights,
// 2 wf/lane/k instead of 4). Weights are read-only loop invariants -> loads
// hoistable, unpack (SHL/AND + mov.b64 dup) runs off the h->z->dh critical
// path on the idle ALU pipe. Crossbar -64 wf/step of ~437 (-15% on the
// binding pipe). h-state stays fp32 (R9 showed bf16 THERE is latency-toxic).

#define T_STEPS 100
#define D_IN    16
#define H_DIM   32
#define HD_DIM  50
#define EULER   10
#define STEP_F  0.1f
#define DTS_F   (1.0f / 24.0f)

#define E       8
#define GRID    1024        // 8192 / 8, 32-thread CTAs

typedef unsigned long long u64;
typedef unsigned int u32;

__device__ __forceinline__ u64 pk2(float lo, float hi) {
    u64 r; asm("mov.b64 %0, {%1, %2};" : "=l"(r) : "f"(lo), "f"(hi)); return r;
}
__device__ __forceinline__ void up2(u64 v, float& a, float& b) {
    asm("mov.b64 {%0, %1}, %2;" : "=f"(a), "=f"(b) : "l"(v));
}
__device__ __forceinline__ void fma2(u64& d, u64 a, u64 b) {
    asm("fma.rn.f32x2 %0, %1, %2, %0;" : "+l"(d) : "l"(a), "l"(b));
}
__device__ __forceinline__ float tanh_fast(float v) {
    float r; asm("tanh.approx.f32 %0, %1;" : "=f"(r) : "f"(v)); return r;
}
__device__ __forceinline__ u64 tanh2(u64 v) {
    float a, b; up2(v, a, b);
    return pk2(tanh_fast(a), tanh_fast(b));
}

// Pack two f32 into bf16x2: hi half = first arg, lo half = second arg.
__device__ __forceinline__ u32 pkbf(float hi, float lo) {
    u32 r; asm("cvt.rn.bf16x2.f32 %0, %1, %2;" : "=r"(r) : "f"(hi), "f"(lo)); return r;
}
// Duplicate lo-half of bf16x2 as f32x2 (w,w).
__device__ __forceinline__ u64 bfdup_lo(u32 p) {
    u32 t = p << 16;
    u64 r; asm("mov.b64 %0, {%1, %1};" : "=l"(r) : "r"(t)); return r;
}
// Duplicate hi-half of bf16x2 as f32x2 (w,w).
__device__ __forceinline__ u64 bfdup_hi(u32 p) {
    u32 t = p & 0xffff0000u;
    u64 r; asm("mov.b64 %0, {%1, %1};" : "=l"(r) : "r"(t)); return r;
}

__global__ void __launch_bounds__(32, 7)
latentode2_kernel(const float* __restrict__ dt,
                  const float* __restrict__ x,
                  const float* __restrict__ W1, const float* __restrict__ b1,
                  const float* __restrict__ W2, const float* __restrict__ b2,
                  const float* __restrict__ W3, const float* __restrict__ b3,
                  const float* __restrict__ W4, const float* __restrict__ b4,
                  float* __restrict__ out)
{
    // sW1x[k*32+j] = (W1[j][k], W1[j+32][k])  f32, k<16 (x part, used 1/10 steps)
    // sW13b[k*32+j] = u64{ lo u32 = bf16x2(W1[j][16+k], W1[j+32][16+k]),
    //                      hi u32 = bf16x2(W3[j][k],    W3[j+32][k]) }   k<32
    __shared__ float2 sW1x[16 * 32];
    __shared__ u64    sW13b[32 * 32];
    // State rows (fp32), split: A = elems 0..3 (two f32x2), B = elems 4..7.
    __shared__ ulonglong2 sXA[D_IN],  sXB[D_IN];
    __shared__ ulonglong2 sHA[H_DIM], sHB[H_DIM];
    __shared__ ulonglong2 sZA[HD_DIM], sZB[HD_DIM];

    const int lane = threadIdx.x;

    for (int idx = lane; idx < 16 * 32; idx += 32) {
        int k = idx >> 5, j = idx & 31;
        float hi = (j + 32 < HD_DIM) ? W1[(j + 32) * 48 + k] : 0.0f;
        sW1x[idx] = make_float2(W1[j * 48 + k], hi);
    }
    for (int idx = lane; idx < 32 * 32; idx += 32) {
        int k = idx >> 5, j = idx & 31;
        float w1lo = W1[j * 48 + 16 + k];
        float w1hi = (j + 32 < HD_DIM) ? W1[(j + 32) * 48 + 16 + k] : 0.0f;
        float w3lo = W3[j * 32 + k];
        float w3hi = W3[(j + 32) * 32 + k];
        u32 w1p = pkbf(w1hi, w1lo);     // lo-half = w1lo, hi-half = w1hi
        u32 w3p = pkbf(w3hi, w3lo);
        sW13b[idx] = (u64)w1p | ((u64)w3p << 32);
    }

    const int e0 = blockIdx.x * E;

    // W2 row in registers (lane = output k of dh).
    float w2r[HD_DIM];
#pragma unroll
    for (int j = 0; j < HD_DIM; j++) w2r[j] = W2[lane * HD_DIM + j];

    const float b1lo = b1[lane];
    const float b1hi = (lane + 32 < HD_DIM) ? b1[lane + 32] : 0.0f;
    const u64 PB3lo = pk2(b3[lane], b3[lane]);
    const u64 PB3hi = pk2(b3[lane + 32], b3[lane + 32]);
    const float b2s = b2[lane];
    const u64 PB2 = pk2(b2s, b2s);
    const float b4v = b4[0];
    const float w4a = W4[lane];
    const float w4b = W4[lane + 32];

    // h state (8 elems, own row) in registers + fp32 SMEM mirror.
    float h0 = 0, h1 = 0, h2 = 0, h3 = 0, h4 = 0, h5 = 0, h6 = 0, h7 = 0;
    sHA[lane] = make_ulonglong2(0ull, 0ull);
    sHB[lane] = make_ulonglong2(0ull, 0ull);
    __syncwarp();

    const float2* dt2 = (const float2*)dt;

#pragma unroll 1
    for (int t = 0; t < T_STEPS; t++) {
        // Stage x rows (lanes 0..15 handle feature = lane).
        if (lane < D_IN) {
            float xv[E];
#pragma unroll
            for (int e = 0; e < E; e++)
                xv[e] = x[((e0 + e) * T_STEPS + t) * D_IN + lane];
            sXA[lane] = make_ulonglong2(pk2(xv[0], xv[1]), pk2(xv[2], xv[3]));
            sXB[lane] = make_ulonglong2(pk2(xv[4], xv[5]), pk2(xv[6], xv[7]));
        }
        float cs[E];
#pragma unroll
        for (int e = 0; e < E; e++) {
            float2 d = dt2[(e0 + e) * T_STEPS + t];
            cs[e] = STEP_F * ((d.y - d.x) * DTS_F);
        }
        __syncwarp();

        // Hoisted: zx = b1 + x @ W1x^T (fp32 weights; reused for 10 steps).
        u64 zxj01 = pk2(b1lo, b1lo), zxj23 = zxj01, zxj45 = zxj01, zxj67 = zxj01;
        u64 zxk01 = pk2(b1hi, b1hi), zxk23 = zxk01, zxk45 = zxk01, zxk67 = zxk01;
#pragma unroll
        for (int k = 0; k < D_IN; k++) {
            ulonglong2 vA = sXA[k], vB = sXB[k];
            float2 w = sW1x[k * 32 + lane];
            u64 wl = pk2(w.x, w.x), wh = pk2(w.y, w.y);
            fma2(zxj01, vA.x, wl); fma2(zxj23, vA.y, wl);
            fma2(zxj45, vB.x, wl); fma2(zxj67, vB.y, wl);
            fma2(zxk01, vA.x, wh); fma2(zxk23, vA.y, wh);
            fma2(zxk45, vB.x, wh); fma2(zxk67, vB.y, wh);
        }

        // Per-lane dy partial sums across all Euler steps (y has no feedback).
        float p0 = 0, p1 = 0, p2 = 0, p3 = 0, p4 = 0, p5 = 0, p6 = 0, p7 = 0;

#pragma unroll 1
        for (int s = 0; s < EULER; s++) {
            u64 zj01 = zxj01, zj23 = zxj23, zj45 = zxj45, zj67 = zxj67;
            u64 zk01 = zxk01, zk23 = zxk23, zk45 = zxk45, zk67 = zxk67;
            u64 gj01 = PB3lo, gj23 = PB3lo, gj45 = PB3lo, gj67 = PB3lo;
            u64 gk01 = PB3hi, gk23 = PB3hi, gk45 = PB3hi, gk67 = PB3hi;

            // Fused: z1 += h @ W1h^T ; g = b3 + h @ W3^T
            // h fp32 broadcast (latency-critical); weights bf16 u64 (hoistable).
#pragma unroll
            for (int k = 0; k < H_DIM; k++) {
                ulonglong2 vA = sHA[k], vB = sHB[k];
                u64 wpair = sW13b[k * 32 + lane];
                u32 w1p, w3p;
                asm("mov.b64 {%0, %1}, %2;" : "=r"(w1p), "=r"(w3p) : "l"(wpair));
                u64 w1l = bfdup_lo(w1p), w1h = bfdup_hi(w1p);
                u64 w3l = bfdup_lo(w3p), w3h = bfdup_hi(w3p);
                fma2(zj01, vA.x, w1l); fma2(zj23, vA.y, w1l);
                fma2(zj45, vB.x, w1l); fma2(zj67, vB.y, w1l);
                fma2(zk01, vA.x, w1h); fma2(zk23, vA.y, w1h);
                fma2(zk45, vB.x, w1h); fma2(zk67, vB.y, w1h);
                fma2(gj01, vA.x, w3l); fma2(gj23, vA.y, w3l);
                fma2(gj45, vB.x, w3l); fma2(gj67, vB.y, w3l);
                fma2(gk01, vA.x, w3h); fma2(gk23, vA.y, w3h);
                fma2(gk45, vB.x, w3h); fma2(gk67, vB.y, w3h);
            }

            // z = tanh(z1-pre), publish fp32 rows lane and lane+32.
            sZA[lane] = make_ulonglong2(tanh2(zj01), tanh2(zj23));
            sZB[lane] = make_ulonglong2(tanh2(zj45), tanh2(zj67));
            if (lane + 32 < HD_DIM) {
                sZA[lane + 32] = make_ulonglong2(tanh2(zk01), tanh2(zk23));
                sZB[lane + 32] = make_ulonglong2(tanh2(zk45), tanh2(zk67));
            }
            __syncwarp();   // z published; h reads of this step done

            // dy partial accumulation.
            {
                float a, b, c, d;
                up2(gj01, a, b); up2(gk01, c, d);
                p0 = fmaf(tanh_fast(a), w4a, fmaf(tanh_fast(c), w4b, p0));
                p1 = fmaf(tanh_fast(b), w4a, fmaf(tanh_fast(d), w4b, p1));
                up2(gj23, a, b); up2(gk23, c, d);
                p2 = fmaf(tanh_fast(a), w4a, fmaf(tanh_fast(c), w4b, p2));
                p3 = fmaf(tanh_fast(b), w4a, fmaf(tanh_fast(d), w4b, p3));
                up2(gj45, a, b); up2(gk45, c, d);
                p4 = fmaf(tanh_fast(a), w4a, fmaf(tanh_fast(c), w4b, p4));
                p5 = fmaf(tanh_fast(b), w4a, fmaf(tanh_fast(d), w4b, p5));
                up2(gj67, a, b); up2(gk67, c, d);
                p6 = fmaf(tanh_fast(a), w4a, fmaf(tanh_fast(c), w4b, p6));
                p7 = fmaf(tanh_fast(b), w4a, fmaf(tanh_fast(d), w4b, p7));
            }

            // dh_pre = b2 + z @ W2^T (out k = lane), W2 row in registers.
            u64 d01 = PB2, d23 = PB2, d45 = PB2, d67 = PB2;
#pragma unroll
            for (int j = 0; j < HD_DIM; j++) {
                ulonglong2 zA = sZA[j], zB = sZB[j];
                u64 wd = pk2(w2r[j], w2r[j]);
                fma2(d01, zA.x, wd); fma2(d23, zA.y, wd);
                fma2(d45, zB.x, wd); fma2(d67, zB.y, wd);
            }

            // h Euler update (fp32 master copy).
            {
                float a, b;
                up2(d01, a, b); h0 = fmaf(cs[0], tanh_fast(a), h0);
                                h1 = fmaf(cs[1], tanh_fast(b), h1);
                up2(d23, a, b); h2 = fmaf(cs[2], tanh_fast(a), h2);
                                h3 = fmaf(cs[3], tanh_fast(b), h3);
                up2(d45, a, b); h4 = fmaf(cs[4], tanh_fast(a), h4);
                                h5 = fmaf(cs[5], tanh_fast(b), h5);
                up2(d67, a, b); h6 = fmaf(cs[6], tanh_fast(a), h6);
                                h7 = fmaf(cs[7], tanh_fast(b), h7);
            }

            sHA[lane] = make_ulonglong2(pk2(h0, h1), pk2(h2, h3));
            sHB[lane] = make_ulonglong2(pk2(h4, h5), pk2(h6, h7));
            __syncwarp();
        }

        // One butterfly reduction per t-step.
#pragma unroll
        for (int off = 16; off > 0; off >>= 1) {
            p0 += __shfl_xor_sync(0xffffffffu, p0, off);
            p1 += __shfl_xor_sync(0xffffffffu, p1, off);
            p2 += __shfl_xor_sync(0xffffffffu, p2, off);
            p3 += __shfl_xor_sync(0xffffffffu, p3, off);
            p4 += __shfl_xor_sync(0xffffffffu, p4, off);
            p5 += __shfl_xor_sync(0xffffffffu, p5, off);
            p6 += __shfl_xor_sync(0xffffffffu, p6, off);
            p7 += __shfl_xor_sync(0xffffffffu, p7, off);
        }

        // y_e = x0_e + cs_e * (P_e + EULER*b4); lanes 0..7 write out.
        {
            float x0A, x1A, x2A, x3A, x4A, x5A, x6A, x7A;
            { ulonglong2 v = sXA[0]; up2(v.x, x0A, x1A); up2(v.y, x2A, x3A); }
            { ulonglong2 v = sXB[0]; up2(v.x, x4A, x5A); up2(v.y, x6A, x7A); }
            const float eb4 = (float)EULER * b4v;
            float yv = fmaf(cs[0], p0 + eb4, x0A);
            if (lane == 1) yv = fmaf(cs[1], p1 + eb4, x1A);
            if (lane == 2) yv = fmaf(cs[2], p2 + eb4, x2A);
            if (lane == 3) yv = fmaf(cs[3], p3 + eb4, x3A);
            if (lane == 4) yv = fmaf(cs[4], p4 + eb4, x4A);
            if (lane == 5) yv = fmaf(cs[5], p5 + eb4, x5A);
            if (lane == 6) yv = fmaf(cs[6], p6 + eb4, x6A);
            if (lane == 7) yv = fmaf(cs[7], p7 + eb4, x7A);
            if (lane < E) out[(e0 + lane) * T_STEPS + t] = yv;
        }
        __syncwarp();   // sX reads done before next t overwrites
    }
}

extern "C" void kernel_launch(void* const* d_in, const int* in_sizes, int n_in,
                              void* d_out, int out_size) {
    (void)in_sizes; (void)n_in; (void)out_size;
    const float* dt = (const float*)d_in[0];
    const float* x  = (const float*)d_in[1];
    const float* W1 = (const float*)d_in[2];
    const float* b1 = (const float*)d_in[3];
    const float* W2 = (const float*)d_in[4];
    const float* b2 = (const float*)d_in[5];
    const float* W3 = (const float*)d_in[6];
    const float* b3 = (const float*)d_in[7];
    const float* W4 = (const float*)d_in[8];
    const float* b4 = (const float*)d_in[9];
    float* out = (float*)d_out;

    latentode2_kernel<<<GRID, 32>>>(
        dt, x, W1, b1, W2, b2, W3, b3, W4, b4, out);
}

// round 16
// speedup vs baseline: 1.7908x; 1.0496x over previous
#include <cuda_runtime.h>

// LatentODE2 R12: R8 (best 2049us) with scheduling trims only:
//  - z-publish made branch-free (sZ padded to 64 rows; lanes 18-31 write
//    never-read zero rows) -> removes BSSY/BSYNC (33-56cyc) x10 per t-step.
//  - dy/p-accumulation hoisted ABOVE sync1 (register-only work on g) so its
//    MUFUs overlap z-tanh/STS latency instead of delaying the dh-loop.
//  - Weights fp32 (R8-exact mix; R11 proved bf16-wt trades are net-negative
//    at this occupancy).

#define T_STEPS 100
#define D_IN    16
#define H_DIM   32
#define HD_DIM  50
#define EULER   10
#define STEP_F  0.1f
#define DTS_F   (1.0f / 24.0f)

#define E       8
#define GRID    1024        // 8192 / 8, 32-thread CTAs

typedef unsigned long long u64;

__device__ __forceinline__ u64 pk2(float lo, float hi) {
    u64 r; asm("mov.b64 %0, {%1, %2};" : "=l"(r) : "f"(lo), "f"(hi)); return r;
}
__device__ __forceinline__ void up2(u64 v, float& a, float& b) {
    asm("mov.b64 {%0, %1}, %2;" : "=f"(a), "=f"(b) : "l"(v));
}
__device__ __forceinline__ void fma2(u64& d, u64 a, u64 b) {
    asm("fma.rn.f32x2 %0, %1, %2, %0;" : "+l"(d) : "l"(a), "l"(b));
}
__device__ __forceinline__ float tanh_fast(float v) {
    float r; asm("tanh.approx.f32 %0, %1;" : "=f"(r) : "f"(v)); return r;
}
__device__ __forceinline__ u64 tanh2(u64 v) {
    float a, b; up2(v, a, b);
    return pk2(tanh_fast(a), tanh_fast(b));
}

__global__ void __launch_bounds__(32, 7)
latentode2_kernel(const float* __restrict__ dt,
                  const float* __restrict__ x,
                  const float* __restrict__ W1, const float* __restrict__ b1,
                  const float* __restrict__ W2, const float* __restrict__ b2,
                  const float* __restrict__ W3, const float* __restrict__ b3,
                  const float* __restrict__ W4, const float* __restrict__ b4,
                  float* __restrict__ out)
{
    // sW1x[k*32+j] = (W1[j][k], W1[j+32][k])                      k<16 (x part)
    // sW13[k*32+j] = (W1[j][16+k], W1[j+32][16+k], W3[j][k], W3[j+32][k])  k<32
    __shared__ float2 sW1x[16 * 32];
    __shared__ float4 sW13[32 * 32];
    // State rows, split: A = elems 0..3 (two f32x2), B = elems 4..7.
    // sZ padded to 64 rows so the publish is branch-free (rows >=50 unread).
    __shared__ ulonglong2 sXA[D_IN],  sXB[D_IN];
    __shared__ ulonglong2 sHA[H_DIM], sHB[H_DIM];
    __shared__ ulonglong2 sZA[64], sZB[64];

    const int lane = threadIdx.x;

    for (int idx = lane; idx < 16 * 32; idx += 32) {
        int k = idx >> 5, j = idx & 31;
        float hi = (j + 32 < HD_DIM) ? W1[(j + 32) * 48 + k] : 0.0f;
        sW1x[idx] = make_float2(W1[j * 48 + k], hi);
    }
    for (int idx = lane; idx < 32 * 32; idx += 32) {
        int k = idx >> 5, j = idx & 31;
        float w1hi = (j + 32 < HD_DIM) ? W1[(j + 32) * 48 + 16 + k] : 0.0f;
        sW13[idx] = make_float4(W1[j * 48 + 16 + k], w1hi,
                                W3[j * 32 + k], W3[(j + 32) * 32 + k]);
    }

    const int e0 = blockIdx.x * E;

    // W2 row in registers (lane = output k of dh).
    float w2r[HD_DIM];
#pragma unroll
    for (int j = 0; j < HD_DIM; j++) w2r[j] = W2[lane * HD_DIM + j];

    const float b1lo = b1[lane];
    const float b1hi = (lane + 32 < HD_DIM) ? b1[lane + 32] : 0.0f;
    const u64 PB3lo = pk2(b3[lane], b3[lane]);
    const u64 PB3hi = pk2(b3[lane + 32], b3[lane + 32]);
    const float b2s = b2[lane];
    const u64 PB2 = pk2(b2s, b2s);
    const float b4v = b4[0];
    const float w4a = W4[lane];
    const float w4b = W4[lane + 32];

    // h state (8 elems, own row) in registers + fp32 SMEM mirror.
    float h0 = 0, h1 = 0, h2 = 0, h3 = 0, h4 = 0, h5 = 0, h6 = 0, h7 = 0;
    sHA[lane] = make_ulonglong2(0ull, 0ull);
    sHB[lane] = make_ulonglong2(0ull, 0ull);
    __syncwarp();

    const float2* dt2 = (const float2*)dt;

#pragma unroll 1
    for (int t = 0; t < T_STEPS; t++) {
        // Stage x rows (lanes 0..15 handle feature = lane).
        if (lane < D_IN) {
            float xv[E];
#pragma unroll
            for (int e = 0; e < E; e++)
                xv[e] = x[((e0 + e) * T_STEPS + t) * D_IN + lane];
            sXA[lane] = make_ulonglong2(pk2(xv[0], xv[1]), pk2(xv[2], xv[3]));
            sXB[lane] = make_ulonglong2(pk2(xv[4], xv[5]), pk2(xv[6], xv[7]));
        }
        float cs[E];
#pragma unroll
        for (int e = 0; e < E; e++) {
            float2 d = dt2[(e0 + e) * T_STEPS + t];
            cs[e] = STEP_F * ((d.y - d.x) * DTS_F);
        }
        __syncwarp();

        // Hoisted: zx = b1 + x @ W1x^T (reused across all 10 Euler steps).
        u64 zxj01 = pk2(b1lo, b1lo), zxj23 = zxj01, zxj45 = zxj01, zxj67 = zxj01;
        u64 zxk01 = pk2(b1hi, b1hi), zxk23 = zxk01, zxk45 = zxk01, zxk67 = zxk01;
#pragma unroll
        for (int k = 0; k < D_IN; k++) {
            ulonglong2 vA = sXA[k], vB = sXB[k];
            float2 w = sW1x[k * 32 + lane];
            u64 wl = pk2(w.x, w.x), wh = pk2(w.y, w.y);
            fma2(zxj01, vA.x, wl); fma2(zxj23, vA.y, wl);
            fma2(zxj45, vB.x, wl); fma2(zxj67, vB.y, wl);
            fma2(zxk01, vA.x, wh); fma2(zxk23, vA.y, wh);
            fma2(zxk45, vB.x, wh); fma2(zxk67, vB.y, wh);
        }

        // Per-lane dy partial sums across all Euler steps (y has no feedback).
        float p0 = 0, p1 = 0, p2 = 0, p3 = 0, p4 = 0, p5 = 0, p6 = 0, p7 = 0;

#pragma unroll 1
        for (int s = 0; s < EULER; s++) {
            u64 zj01 = zxj01, zj23 = zxj23, zj45 = zxj45, zj67 = zxj67;
            u64 zk01 = zxk01, zk23 = zxk23, zk45 = zxk45, zk67 = zxk67;
            u64 gj01 = PB3lo, gj23 = PB3lo, gj45 = PB3lo, gj67 = PB3lo;
            u64 gk01 = PB3hi, gk23 = PB3hi, gk45 = PB3hi, gk67 = PB3hi;

            // Fused: z1 += h @ W1h^T ; g = b3 + h @ W3^T
#pragma unroll
            for (int k = 0; k < H_DIM; k++) {
                ulonglong2 vA = sHA[k], vB = sHB[k];
                float4 w = sW13[k * 32 + lane];
                u64 w1l = pk2(w.x, w.x), w1h = pk2(w.y, w.y);
                u64 w3l = pk2(w.z, w.z), w3h = pk2(w.w, w.w);
                fma2(zj01, vA.x, w1l); fma2(zj23, vA.y, w1l);
                fma2(zj45, vB.x, w1l); fma2(zj67, vB.y, w1l);
                fma2(zk01, vA.x, w1h); fma2(zk23, vA.y, w1h);
                fma2(zk45, vB.x, w1h); fma2(zk67, vB.y, w1h);
                fma2(gj01, vA.x, w3l); fma2(gj23, vA.y, w3l);
                fma2(gj45, vB.x, w3l); fma2(gj67, vB.y, w3l);
                fma2(gk01, vA.x, w3h); fma2(gk23, vA.y, w3h);
                fma2(gk45, vB.x, w3h); fma2(gk67, vB.y, w3h);
            }

            // z = tanh(z1-pre), publish branch-free (rows >= 50 are dead).
            sZA[lane] = make_ulonglong2(tanh2(zj01), tanh2(zj23));
            sZB[lane] = make_ulonglong2(tanh2(zj45), tanh2(zj67));
            sZA[lane + 32] = make_ulonglong2(tanh2(zk01), tanh2(zk23));
            sZB[lane + 32] = make_ulonglong2(tanh2(zk45), tanh2(zk67));

            // dy partial accumulation (register-only, on g) hoisted BEFORE the
            // sync: its MUFUs overlap the z-tanh/STS latency window.
            {
                float a, b, c, d;
                up2(gj01, a, b); up2(gk01, c, d);
                p0 = fmaf(tanh_fast(a), w4a, fmaf(tanh_fast(c), w4b, p0));
                p1 = fmaf(tanh_fast(b), w4a, fmaf(tanh_fast(d), w4b, p1));
                up2(gj23, a, b); up2(gk23, c, d);
                p2 = fmaf(tanh_fast(a), w4a, fmaf(tanh_fast(c), w4b, p2));
                p3 = fmaf(tanh_fast(b), w4a, fmaf(tanh_fast(d), w4b, p3));
                up2(gj45, a, b); up2(gk45, c, d);
                p4 = fmaf(tanh_fast(a), w4a, fmaf(tanh_fast(c), w4b, p4));
                p5 = fmaf(tanh_fast(b), w4a, fmaf(tanh_fast(d), w4b, p5));
                up2(gj67, a, b); up2(gk67, c, d);
                p6 = fmaf(tanh_fast(a), w4a, fmaf(tanh_fast(c), w4b, p6));
                p7 = fmaf(tanh_fast(b), w4a, fmaf(tanh_fast(d), w4b, p7));
            }
            __syncwarp();   // z published; h reads of this step done

            // dh_pre = b2 + z @ W2^T (out k = lane), W2 row in registers.
            u64 d01 = PB2, d23 = PB2, d45 = PB2, d67 = PB2;
#pragma unroll
            for (int j = 0; j < HD_DIM; j++) {
                ulonglong2 zA = sZA[j], zB = sZB[j];
                u64 wd = pk2(w2r[j], w2r[j]);
                fma2(d01, zA.x, wd); fma2(d23, zA.y, wd);
                fma2(d45, zB.x, wd); fma2(d67, zB.y, wd);
            }

            // h Euler update.
            {
                float a, b;
                up2(d01, a, b); h0 = fmaf(cs[0], tanh_fast(a), h0);
                                h1 = fmaf(cs[1], tanh_fast(b), h1);
                up2(d23, a, b); h2 = fmaf(cs[2], tanh_fast(a), h2);
                                h3 = fmaf(cs[3], tanh_fast(b), h3);
                up2(d45, a, b); h4 = fmaf(cs[4], tanh_fast(a), h4);
                                h5 = fmaf(cs[5], tanh_fast(b), h5);
                up2(d67, a, b); h6 = fmaf(cs[6], tanh_fast(a), h6);
                                h7 = fmaf(cs[7], tanh_fast(b), h7);
            }

            sHA[lane] = make_ulonglong2(pk2(h0, h1), pk2(h2, h3));
            sHB[lane] = make_ulonglong2(pk2(h4, h5), pk2(h6, h7));
            __syncwarp();
        }

        // One butterfly reduction per t-step.
#pragma unroll
        for (int off = 16; off > 0; off >>= 1) {
            p0 += __shfl_xor_sync(0xffffffffu, p0, off);
            p1 += __shfl_xor_sync(0xffffffffu, p1, off);
            p2 += __shfl_xor_sync(0xffffffffu, p2, off);
            p3 += __shfl_xor_sync(0xffffffffu, p3, off);
            p4 += __shfl_xor_sync(0xffffffffu, p4, off);
            p5 += __shfl_xor_sync(0xffffffffu, p5, off);
            p6 += __shfl_xor_sync(0xffffffffu, p6, off);
            p7 += __shfl_xor_sync(0xffffffffu, p7, off);
        }

        // y_e = x0_e + cs_e * (P_e + EULER*b4); lanes 0..7 write out.
        {
            float x0A, x1A, x2A, x3A, x4A, x5A, x6A, x7A;
            { ulonglong2 v = sXA[0]; up2(v.x, x0A, x1A); up2(v.y, x2A, x3A); }
            { ulonglong2 v = sXB[0]; up2(v.x, x4A, x5A); up2(v.y, x6A, x7A); }
            const float eb4 = (float)EULER * b4v;
            float yv = fmaf(cs[0], p0 + eb4, x0A);
            if (lane == 1) yv = fmaf(cs[1], p1 + eb4, x1A);
            if (lane == 2) yv = fmaf(cs[2], p2 + eb4, x2A);
            if (lane == 3) yv = fmaf(cs[3], p3 + eb4, x3A);
            if (lane == 4) yv = fmaf(cs[4], p4 + eb4, x4A);
            if (lane == 5) yv = fmaf(cs[5], p5 + eb4, x5A);
            if (lane == 6) yv = fmaf(cs[6], p6 + eb4, x6A);
            if (lane == 7) yv = fmaf(cs[7], p7 + eb4, x7A);
            if (lane < E) out[(e0 + lane) * T_STEPS + t] = yv;
        }
        __syncwarp();   // sX reads done before next t overwrites
    }
}

extern "C" void kernel_launch(void* const* d_in, const int* in_sizes, int n_in,
                              void* d_out, int out_size) {
    (void)in_sizes; (void)n_in; (void)out_size;
    const float* dt = (const float*)d_in[0];
    const float* x  = (const float*)d_in[1];
    const float* W1 = (const float*)d_in[2];
    const float* b1 = (const float*)d_in[3];
    const float* W2 = (const float*)d_in[4];
    const float* b2 = (const float*)d_in[5];
    const float* W3 = (const float*)d_in[6];
    const float* b3 = (const float*)d_in[7];
    const float* W4 = (const float*)d_in[8];
    const float* b4 = (const float*)d_in[9];
    float* out = (float*)d_out;

    latentode2_kernel<<<GRID, 32>>>(
        dt, x, W1, b1, W2, b2, W3, b3, W4, b4, out);
}

// round 17
// speedup vs baseline: 1.8514x; 1.0339x over previous
#include <cuda_runtime.h>

// LatentODE2 R13: R8 (best 2049us) with REGISTER-PRESSURE RELIEF only.
// R8/R12 both sat at regs=255 with L2~0.8% (live spill at the cliff), which
// blocks ptxas from software-pipelining the 32 unrolled weight/state loads.
// Changes vs R8 (hot-path traffic +~1%, numerics identical):
//  - cs[8] moved to SMEM (lanes 0-7 stage once per t; h-update reloads as two
//    bcast LDS.128 per step into short-lived regs).  -8 long-lived regs.
//  - PB2/PB3lo/PB3hi held as scalars, re-packed per step (1 pk2 each). -6 regs.
// Everything else identical to R8.

#define T_STEPS 100
#define D_IN    16
#define H_DIM   32
#define HD_DIM  50
#define EULER   10
#define STEP_F  0.1f
#define DTS_F   (1.0f / 24.0f)

#define E       8
#define GRID    1024        // 8192 / 8, 32-thread CTAs

typedef unsigned long long u64;

__device__ __forceinline__ u64 pk2(float lo, float hi) {
    u64 r; asm("mov.b64 %0, {%1, %2};" : "=l"(r) : "f"(lo), "f"(hi)); return r;
}
__device__ __forceinline__ void up2(u64 v, float& a, float& b) {
    asm("mov.b64 {%0, %1}, %2;" : "=f"(a), "=f"(b) : "l"(v));
}
__device__ __forceinline__ void fma2(u64& d, u64 a, u64 b) {
    asm("fma.rn.f32x2 %0, %1, %2, %0;" : "+l"(d) : "l"(a), "l"(b));
}
__device__ __forceinline__ float tanh_fast(float v) {
    float r; asm("tanh.approx.f32 %0, %1;" : "=f"(r) : "f"(v)); return r;
}
__device__ __forceinline__ u64 tanh2(u64 v) {
    float a, b; up2(v, a, b);
    return pk2(tanh_fast(a), tanh_fast(b));
}

__global__ void __launch_bounds__(32, 7)
latentode2_kernel(const float* __restrict__ dt,
                  const float* __restrict__ x,
                  const float* __restrict__ W1, const float* __restrict__ b1,
                  const float* __restrict__ W2, const float* __restrict__ b2,
                  const float* __restrict__ W3, const float* __restrict__ b3,
                  const float* __restrict__ W4, const float* __restrict__ b4,
                  float* __restrict__ out)
{
    // sW1x[k*32+j] = (W1[j][k], W1[j+32][k])                      k<16 (x part)
    // sW13[k*32+j] = (W1[j][16+k], W1[j+32][16+k], W3[j][k], W3[j+32][k])  k<32
    __shared__ float2 sW1x[16 * 32];
    __shared__ float4 sW13[32 * 32];
    // State rows, split: A = elems 0..3 (two f32x2), B = elems 4..7.
    __shared__ ulonglong2 sXA[D_IN],  sXB[D_IN];
    __shared__ ulonglong2 sHA[H_DIM], sHB[H_DIM];
    __shared__ ulonglong2 sZA[HD_DIM], sZB[HD_DIM];
    __shared__ float sCS[E];      // per-element Euler scale for this t

    const int lane = threadIdx.x;

    for (int idx = lane; idx < 16 * 32; idx += 32) {
        int k = idx >> 5, j = idx & 31;
        float hi = (j + 32 < HD_DIM) ? W1[(j + 32) * 48 + k] : 0.0f;
        sW1x[idx] = make_float2(W1[j * 48 + k], hi);
    }
    for (int idx = lane; idx < 32 * 32; idx += 32) {
        int k = idx >> 5, j = idx & 31;
        float w1hi = (j + 32 < HD_DIM) ? W1[(j + 32) * 48 + 16 + k] : 0.0f;
        sW13[idx] = make_float4(W1[j * 48 + 16 + k], w1hi,
                                W3[j * 32 + k], W3[(j + 32) * 32 + k]);
    }

    const int e0 = blockIdx.x * E;

    // W2 row in registers (lane = output k of dh).
    float w2r[HD_DIM];
#pragma unroll
    for (int j = 0; j < HD_DIM; j++) w2r[j] = W2[lane * HD_DIM + j];

    const float b1lo = b1[lane];
    const float b1hi = (lane + 32 < HD_DIM) ? b1[lane + 32] : 0.0f;
    const float b3lo = b3[lane];
    const float b3hi = b3[lane + 32];
    const float b2s  = b2[lane];
    const float b4v  = b4[0];
    const float w4a  = W4[lane];
    const float w4b  = W4[lane + 32];

    // h state (8 elems, own row) in registers + fp32 SMEM mirror.
    float h0 = 0, h1 = 0, h2 = 0, h3 = 0, h4 = 0, h5 = 0, h6 = 0, h7 = 0;
    sHA[lane] = make_ulonglong2(0ull, 0ull);
    sHB[lane] = make_ulonglong2(0ull, 0ull);
    __syncwarp();

    const float2* dt2 = (const float2*)dt;

#pragma unroll 1
    for (int t = 0; t < T_STEPS; t++) {
        // Stage x rows (lanes 0..15 handle feature = lane).
        if (lane < D_IN) {
            float xv[E];
#pragma unroll
            for (int e = 0; e < E; e++)
                xv[e] = x[((e0 + e) * T_STEPS + t) * D_IN + lane];
            sXA[lane] = make_ulonglong2(pk2(xv[0], xv[1]), pk2(xv[2], xv[3]));
            sXB[lane] = make_ulonglong2(pk2(xv[4], xv[5]), pk2(xv[6], xv[7]));
        }
        // Stage cs (lane e < 8 handles element e): one coalesced LDG.64.
        if (lane < E) {
            float2 d = dt2[(e0 + lane) * T_STEPS + t];
            sCS[lane] = STEP_F * ((d.y - d.x) * DTS_F);
        }
        __syncwarp();

        // Hoisted: zx = b1 + x @ W1x^T (reused across all 10 Euler steps).
        u64 zxj01 = pk2(b1lo, b1lo), zxj23 = zxj01, zxj45 = zxj01, zxj67 = zxj01;
        u64 zxk01 = pk2(b1hi, b1hi), zxk23 = zxk01, zxk45 = zxk01, zxk67 = zxk01;
#pragma unroll
        for (int k = 0; k < D_IN; k++) {
            ulonglong2 vA = sXA[k], vB = sXB[k];
            float2 w = sW1x[k * 32 + lane];
            u64 wl = pk2(w.x, w.x), wh = pk2(w.y, w.y);
            fma2(zxj01, vA.x, wl); fma2(zxj23, vA.y, wl);
            fma2(zxj45, vB.x, wl); fma2(zxj67, vB.y, wl);
            fma2(zxk01, vA.x, wh); fma2(zxk23, vA.y, wh);
            fma2(zxk45, vB.x, wh); fma2(zxk67, vB.y, wh);
        }

        // Per-lane dy partial sums across all Euler steps (y has no feedback).
        float p0 = 0, p1 = 0, p2 = 0, p3 = 0, p4 = 0, p5 = 0, p6 = 0, p7 = 0;

#pragma unroll 1
        for (int s = 0; s < EULER; s++) {
            u64 zj01 = zxj01, zj23 = zxj23, zj45 = zxj45, zj67 = zxj67;
            u64 zk01 = zxk01, zk23 = zxk23, zk45 = zxk45, zk67 = zxk67;
            const u64 gb3lo = pk2(b3lo, b3lo);
            const u64 gb3hi = pk2(b3hi, b3hi);
            u64 gj01 = gb3lo, gj23 = gb3lo, gj45 = gb3lo, gj67 = gb3lo;
            u64 gk01 = gb3hi, gk23 = gb3hi, gk45 = gb3hi, gk67 = gb3hi;

            // Fused: z1 += h @ W1h^T ; g = b3 + h @ W3^T
#pragma unroll
            for (int k = 0; k < H_DIM; k++) {
                ulonglong2 vA = sHA[k], vB = sHB[k];
                float4 w = sW13[k * 32 + lane];
                u64 w1l = pk2(w.x, w.x), w1h = pk2(w.y, w.y);
                u64 w3l = pk2(w.z, w.z), w3h = pk2(w.w, w.w);
                fma2(zj01, vA.x, w1l); fma2(zj23, vA.y, w1l);
                fma2(zj45, vB.x, w1l); fma2(zj67, vB.y, w1l);
                fma2(zk01, vA.x, w1h); fma2(zk23, vA.y, w1h);
                fma2(zk45, vB.x, w1h); fma2(zk67, vB.y, w1h);
                fma2(gj01, vA.x, w3l); fma2(gj23, vA.y, w3l);
                fma2(gj45, vB.x, w3l); fma2(gj67, vB.y, w3l);
                fma2(gk01, vA.x, w3h); fma2(gk23, vA.y, w3h);
                fma2(gk45, vB.x, w3h); fma2(gk67, vB.y, w3h);
            }

            // z = tanh(z1-pre), publish rows lane and lane+32.
            sZA[lane] = make_ulonglong2(tanh2(zj01), tanh2(zj23));
            sZB[lane] = make_ulonglong2(tanh2(zj45), tanh2(zj67));
            if (lane + 32 < HD_DIM) {
                sZA[lane + 32] = make_ulonglong2(tanh2(zk01), tanh2(zk23));
                sZB[lane + 32] = make_ulonglong2(tanh2(zk45), tanh2(zk67));
            }
            __syncwarp();   // z published; h reads of this step done

            // dy partial accumulation.
            {
                float a, b, c, d;
                up2(gj01, a, b); up2(gk01, c, d);
                p0 = fmaf(tanh_fast(a), w4a, fmaf(tanh_fast(c), w4b, p0));
                p1 = fmaf(tanh_fast(b), w4a, fmaf(tanh_fast(d), w4b, p1));
                up2(gj23, a, b); up2(gk23, c, d);
                p2 = fmaf(tanh_fast(a), w4a, fmaf(tanh_fast(c), w4b, p2));
                p3 = fmaf(tanh_fast(b), w4a, fmaf(tanh_fast(d), w4b, p3));
                up2(gj45, a, b); up2(gk45, c, d);
                p4 = fmaf(tanh_fast(a), w4a, fmaf(tanh_fast(c), w4b, p4));
                p5 = fmaf(tanh_fast(b), w4a, fmaf(tanh_fast(d), w4b, p5));
                up2(gj67, a, b); up2(gk67, c, d);
                p6 = fmaf(tanh_fast(a), w4a, fmaf(tanh_fast(c), w4b, p6));
                p7 = fmaf(tanh_fast(b), w4a, fmaf(tanh_fast(d), w4b, p7));
            }

            // dh_pre = b2 + z @ W2^T (out k = lane), W2 row in registers.
            const u64 PB2 = pk2(b2s, b2s);
            u64 d01 = PB2, d23 = PB2, d45 = PB2, d67 = PB2;
#pragma unroll
            for (int j = 0; j < HD_DIM; j++) {
                ulonglong2 zA = sZA[j], zB = sZB[j];
                u64 wd = pk2(w2r[j], w2r[j]);
                fma2(d01, zA.x, wd); fma2(d23, zA.y, wd);
                fma2(d45, zB.x, wd); fma2(d67, zB.y, wd);
            }

            // h Euler update; cs from SMEM (short-lived regs).
            {
                float4 c0 = *(const float4*)&sCS[0];
                float4 c1 = *(const float4*)&sCS[4];
                float a, b;
                up2(d01, a, b); h0 = fmaf(c0.x, tanh_fast(a), h0);
                                h1 = fmaf(c0.y, tanh_fast(b), h1);
                up2(d23, a, b); h2 = fmaf(c0.z, tanh_fast(a), h2);
                                h3 = fmaf(c0.w, tanh_fast(b), h3);
                up2(d45, a, b); h4 = fmaf(c1.x, tanh_fast(a), h4);
                                h5 = fmaf(c1.y, tanh_fast(b), h5);
                up2(d67, a, b); h6 = fmaf(c1.z, tanh_fast(a), h6);
                                h7 = fmaf(c1.w, tanh_fast(b), h7);
            }

            sHA[lane] = make_ulonglong2(pk2(h0, h1), pk2(h2, h3));
            sHB[lane] = make_ulonglong2(pk2(h4, h5), pk2(h6, h7));
            __syncwarp();
        }

        // One butterfly reduction per t-step.
#pragma unroll
        for (int off = 16; off > 0; off >>= 1) {
            p0 += __shfl_xor_sync(0xffffffffu, p0, off);
            p1 += __shfl_xor_sync(0xffffffffu, p1, off);
            p2 += __shfl_xor_sync(0xffffffffu, p2, off);
            p3 += __shfl_xor_sync(0xffffffffu, p3, off);
            p4 += __shfl_xor_sync(0xffffffffu, p4, off);
            p5 += __shfl_xor_sync(0xffffffffu, p5, off);
            p6 += __shfl_xor_sync(0xffffffffu, p6, off);
            p7 += __shfl_xor_sync(0xffffffffu, p7, off);
        }

        // y_e = x0_e + cs_e * (P_e + EULER*b4); lanes 0..7 write out.
        {
            float x0A, x1A, x2A, x3A, x4A, x5A, x6A, x7A;
            { ulonglong2 v = sXA[0]; up2(v.x, x0A, x1A); up2(v.y, x2A, x3A); }
            { ulonglong2 v = sXB[0]; up2(v.x, x4A, x5A); up2(v.y, x6A, x7A); }
            float4 c0 = *(const float4*)&sCS[0];
            float4 c1 = *(const float4*)&sCS[4];
            const float eb4 = (float)EULER * b4v;
            float yv = fmaf(c0.x, p0 + eb4, x0A);
            if (lane == 1) yv = fmaf(c0.y, p1 + eb4, x1A);
            if (lane == 2) yv = fmaf(c0.z, p2 + eb4, x2A);
            if (lane == 3) yv = fmaf(c0.w, p3 + eb4, x3A);
            if (lane == 4) yv = fmaf(c1.x, p4 + eb4, x4A);
            if (lane == 5) yv = fmaf(c1.y, p5 + eb4, x5A);
            if (lane == 6) yv = fmaf(c1.z, p6 + eb4, x6A);
            if (lane == 7) yv = fmaf(c1.w, p7 + eb4, x7A);
            if (lane < E) out[(e0 + lane) * T_STEPS + t] = yv;
        }
        __syncwarp();   // sX/sCS reads done before next t overwrites
    }
}

extern "C" void kernel_launch(void* const* d_in, const int* in_sizes, int n_in,
                              void* d_out, int out_size) {
    (void)in_sizes; (void)n_in; (void)out_size;
    const float* dt = (const float*)d_in[0];
    const float* x  = (const float*)d_in[1];
    const float* W1 = (const float*)d_in[2];
    const float* b1 = (const float*)d_in[3];
    const float* W2 = (const float*)d_in[4];
    const float* b2 = (const float*)d_in[5];
    const float* W3 = (const float*)d_in[6];
    const float* b3 = (const float*)d_in[7];
    const float* W4 = (const float*)d_in[8];
    const float* b4 = (const float*)d_in[9];
    float* out = (float*)d_out;

    latentode2_kernel<<<GRID, 32>>>(
        dt, x, W1, b1, W2, b2, W3, b3, W4, b4, out);
}